// round 13
// baseline (speedup 1.0000x reference)
#include <cuda_runtime.h>
#include <cuda_bf16.h>
#include <cfloat>
#include <stdint.h>
#include <math.h>

#define NB 16384
#define NKEY 8192
#define ND 1024
#define BM 128
#define BN 256
#define BK 64
#define STAGES 4
#define NSM 148
#define NPAIRS 4096                // 128 qtiles x 32 keytiles
#define THREADS 512

#define ROWB 144                   // 128B data + 16B pad
#define A_BYTES (BM * ROWB)        // 18432
#define B_BYTES (BN * ROWB)        // 36864
#define STAGE_BYTES (A_BYTES + B_BYTES)   // 55296
#define SMEM_BYTES (STAGES * STAGE_BYTES) // 221184

// ---------------- scratch ----------------
__device__ __nv_bfloat16 g_qn16[(size_t)NB * ND];
__device__ __nv_bfloat16 g_kn16[(size_t)NKEY * ND];
__device__ float g_qinv[NB];
__device__ float g_kinv[NKEY];
// raw per-slice top-4 dump: [cta][seg<=2][row 128][slice 16][4] (val, idx)
__device__ float2 g_dump[(size_t)NSM * 2 * BM * 64];

// ---------------- helpers ----------------
static __device__ __forceinline__ uint32_t smem_u32(const void* p) {
    return (uint32_t)__cvta_generic_to_shared(p);
}
static __device__ __forceinline__ void cp16(uint32_t dst, const void* src) {
    asm volatile("cp.async.cg.shared.global [%0], [%1], 16;" :: "r"(dst), "l"(src));
}
static __device__ __forceinline__ void cp_commit() {
    asm volatile("cp.async.commit_group;" ::: "memory");
}
static __device__ __forceinline__ void cp_wait2() {
    asm volatile("cp.async.wait_group 2;" ::: "memory");
}
static __device__ __forceinline__ void ldm_x4(uint32_t* r, uint32_t a) {
    asm volatile("ldmatrix.sync.aligned.m8n8.x4.shared.b16 {%0,%1,%2,%3}, [%4];"
                 : "=r"(r[0]), "=r"(r[1]), "=r"(r[2]), "=r"(r[3]) : "r"(a));
}
static __device__ __forceinline__ void mma16816(float* d, const uint32_t* a,
                                                const uint32_t* b) {
    asm volatile(
        "mma.sync.aligned.m16n8k16.row.col.f32.bf16.bf16.f32 "
        "{%0,%1,%2,%3}, {%4,%5,%6,%7}, {%8,%9}, {%0,%1,%2,%3};"
        : "+f"(d[0]), "+f"(d[1]), "+f"(d[2]), "+f"(d[3])
        : "r"(a[0]), "r"(a[1]), "r"(a[2]), "r"(a[3]), "r"(b[0]), "r"(b[1]));
}

// ---------------- normalize -> bf16 (queries + keys fused) ----------------
__global__ void norm_kernel(const float* __restrict__ q, const float* __restrict__ k) {
    int row = blockIdx.x;
    const float* in;
    __nv_bfloat16* out;
    float* invp;
    int r;
    if (row < NB) { in = q; out = g_qn16; invp = g_qinv; r = row; }
    else          { in = k; out = g_kn16; invp = g_kinv; r = row - NB; }
    int t = threadIdx.x;
    float4 v = reinterpret_cast<const float4*>(in)[(size_t)r * (ND / 4) + t];
    float ss = v.x * v.x + v.y * v.y + v.z * v.z + v.w * v.w;
    #pragma unroll
    for (int o = 16; o; o >>= 1) ss += __shfl_xor_sync(0xffffffffu, ss, o);
    __shared__ float wsum[8];
    if ((t & 31) == 0) wsum[t >> 5] = ss;
    __syncthreads();
    float tot = 0.0f;
    #pragma unroll
    for (int i = 0; i < 8; ++i) tot += wsum[i];
    float inv = 1.0f / fmaxf(sqrtf(tot), 1e-12f);
    if (t == 0) invp[r] = inv;
    union { __nv_bfloat162 h2[2]; uint2 u; } pk;
    pk.h2[0] = __floats2bfloat162_rn(v.x * inv, v.y * inv);
    pk.h2[1] = __floats2bfloat162_rn(v.z * inv, v.w * inv);
    reinterpret_cast<uint2*>(out)[(size_t)r * (ND / 4) + t] = pk.u;
}

// ---------------- top-4 insert ----------------
static __device__ __forceinline__ void top4_insert(float* tv, int* ti, float v, int idx) {
    if (v > tv[3]) {
        tv[3] = v; ti[3] = idx;
        #pragma unroll
        for (int s = 3; s > 0; --s) {
            if (tv[s] > tv[s - 1]) {
                float tf = tv[s]; tv[s] = tv[s - 1]; tv[s - 1] = tf;
                int tn = ti[s]; ti[s] = ti[s - 1]; ti[s - 1] = tn;
            }
        }
    }
}

// ---- bf16 sim GEMM: 148 CTAs over 4096 (qtile,keytile) pairs, raw dump ----
__global__ __launch_bounds__(THREADS, 1) void simtopk_kernel() {
    extern __shared__ char dynsmem[];
    const uint32_t sbase = smem_u32(dynsmem);
    const int tid = threadIdx.x;
    const int wid = tid >> 5, lane = tid & 31;
    const int warp_m = wid & 3;     // rows warp_m*32
    const int warp_n = wid >> 2;    // cols warp_n*64
    const int cta = blockIdx.x;

    const int p0 = (cta * NPAIRS) / NSM;
    const int p1 = ((cta + 1) * NPAIRS) / NSM;
    const int nsteps = (p1 - p0) * 16;

    float acc[2][8][4];
    float tv[4][4]; int ti[4][4];
    #pragma unroll
    for (int mf = 0; mf < 2; ++mf)
        #pragma unroll
        for (int nf = 0; nf < 8; ++nf)
            #pragma unroll
            for (int e = 0; e < 4; ++e) acc[mf][nf][e] = 0.0f;
    #pragma unroll
    for (int r = 0; r < 4; ++r)
        #pragma unroll
        for (int e = 0; e < 4; ++e) { tv[r][e] = -FLT_MAX; ti[r][e] = 0; }

    auto issue_loads = [&](int j) {
        const int pair = p0 + (j >> 4);
        const int qb = (pair >> 5) * BM;
        const int kb = (pair & 31) * BN;
        const int kcol = (j & 15) * BK;
        const uint32_t aS = sbase + (uint32_t)(j & 3) * STAGE_BYTES;
        const uint32_t bS = aS + A_BYTES;
        #pragma unroll
        for (int u = 0; u < 2; ++u) {   // A: 128 rows x 8 chunks of 16B
            int idx = tid + 512 * u;
            int row = idx >> 3, c = idx & 7;
            cp16(aS + row * ROWB + c * 16,
                 g_qn16 + (size_t)(qb + row) * ND + kcol + c * 8);
        }
        #pragma unroll
        for (int u = 0; u < 4; ++u) {   // B: 256 rows x 8 chunks
            int idx = tid + 512 * u;
            int row = idx >> 3, c = idx & 7;
            cp16(bS + row * ROWB + c * 16,
                 g_kn16 + (size_t)(kb + row) * ND + kcol + c * 8);
        }
    };

    #pragma unroll
    for (int j = 0; j < STAGES - 1; ++j) { issue_loads(j); cp_commit(); }

    for (int i = 0; i < nsteps; ++i) {
        cp_wait2();
        __syncthreads();
        if (i + 3 < nsteps) issue_loads(i + 3);
        cp_commit();

        const uint32_t aS = sbase + (uint32_t)(i & 3) * STAGE_BYTES;
        const uint32_t bS = aS + A_BYTES;
        const uint32_t aAddr = aS + (warp_m * 32 + (lane & 15)) * ROWB + (lane >> 4) * 16;
        const uint32_t bAddr = bS + (warp_n * 64 + (lane & 7) + (lane >> 4) * 8) * ROWB
                               + ((lane >> 3) & 1) * 16;
        #pragma unroll
        for (int kf = 0; kf < 4; ++kf) {
            uint32_t af[2][4];
            ldm_x4(af[0], aAddr + kf * 32);
            ldm_x4(af[1], aAddr + 16 * ROWB + kf * 32);
            #pragma unroll
            for (int ng = 0; ng < 4; ++ng) {
                uint32_t bf[4];
                ldm_x4(bf, bAddr + ng * 16 * ROWB + kf * 32);
                mma16816(acc[0][2 * ng],     af[0], bf + 0);
                mma16816(acc[0][2 * ng + 1], af[0], bf + 2);
                mma16816(acc[1][2 * ng],     af[1], bf + 0);
                mma16816(acc[1][2 * ng + 1], af[1], bf + 2);
            }
        }

        if ((i & 15) == 15) {   // keytile done: fold into per-slice top-4
            const int pair = p0 + (i >> 4);
            const int cb = (pair & 31) * BN + warp_n * 64 + (lane & 3) * 2;
            #pragma unroll
            for (int mf = 0; mf < 2; ++mf)
                #pragma unroll
                for (int nf = 0; nf < 8; ++nf) {
                    float* a4 = acc[mf][nf];
                    const int cc = cb + nf * 8;
                    top4_insert(tv[mf * 2],     ti[mf * 2],     a4[0], cc);
                    top4_insert(tv[mf * 2],     ti[mf * 2],     a4[1], cc + 1);
                    top4_insert(tv[mf * 2 + 1], ti[mf * 2 + 1], a4[2], cc);
                    top4_insert(tv[mf * 2 + 1], ti[mf * 2 + 1], a4[3], cc + 1);
                    a4[0] = a4[1] = a4[2] = a4[3] = 0.0f;
                }
            // segment (qtile) boundary or end: raw-dump tv/ti, reset
            if (i == nsteps - 1 || (((pair + 1) >> 5) != (pair >> 5))) {
                const int seg = (pair >> 5) - (p0 >> 5);   // 0 or 1
                const int slice = warp_n * 4 + (lane & 3);
                #pragma unroll
                for (int rp = 0; rp < 4; ++rp) {
                    int row = warp_m * 32 + (rp >> 1) * 16 + (rp & 1) * 8 + (lane >> 2);
                    size_t base = ((size_t)(cta * 2 + seg) * BM + row) * 64 + slice * 4;
                    #pragma unroll
                    for (int e = 0; e < 4; ++e)
                        g_dump[base + e] = make_float2(tv[rp][e],
                                                       __int_as_float(ti[rp][e]));
                }
                #pragma unroll
                for (int r = 0; r < 4; ++r)
                    #pragma unroll
                    for (int e = 0; e < 4; ++e) { tv[r][e] = -FLT_MAX; ti[r][e] = 0; }
            }
        }
    }
}

// ------- rescore: merge covering-CTA dumps -> bf16 top-8 -> fp32 top-4 -------
__global__ __launch_bounds__(256, 4) void rescore_kernel(const float* __restrict__ q,
                                                         const float* __restrict__ keys,
                                                         const float* __restrict__ values,
                                                         float* __restrict__ out) {
    const int b = blockIdx.x;
    const int qt = b >> 7, row = b & 127;
    const int tid = threadIdx.x, wid = tid >> 5, lane = tid & 31;
    __shared__ float sq[ND];       // staged q row (4KB)
    __shared__ int scand[8];
    __shared__ float ssim[8];
    __shared__ int sidx[8];
    __shared__ float sw[4];
    __shared__ int si[4];

    // stage the q row into smem first: overlaps merge-warp latency below
    {
        const float4* q4 = reinterpret_cast<const float4*>(q) + (size_t)b * (ND / 4);
        reinterpret_cast<float4*>(sq)[tid] = q4[tid];
    }

    if (tid < 32) {   // one warp merges up to 3 covering CTAs x 64 entries
        const int pfirst = qt * 32, plast = pfirst + 31;
        int cmin = (pfirst * NSM) >> 12;
        while ((cmin + 1) * NPAIRS / NSM <= pfirst) ++cmin;
        while (cmin * NPAIRS / NSM > pfirst) --cmin;
        int cmax = (plast * NSM) >> 12;
        while ((cmax + 1) * NPAIRS / NSM <= plast) ++cmax;
        while (cmax * NPAIRS / NSM > plast) --cmax;
        const int ncov = cmax - cmin + 1;      // 2 or 3

        float lv[6]; int lk[6];
        #pragma unroll
        for (int s = 0; s < 6; ++s) { lv[s] = -FLT_MAX; lk[s] = 0x7fffffff; }
        for (int ci = 0; ci < ncov; ++ci) {
            int c = cmin + ci;
            int p0c = c * NPAIRS / NSM;
            int seg = qt - (p0c >> 5);
            const float2* base = g_dump + ((size_t)(c * 2 + seg) * BM + row) * 64;
            float2 e0 = base[lane * 2];
            float2 e1 = base[lane * 2 + 1];
            lv[ci * 2] = e0.x;     lk[ci * 2] = __float_as_int(e0.y);
            lv[ci * 2 + 1] = e1.x; lk[ci * 2 + 1] = __float_as_int(e1.y);
        }
        unsigned used = 0;
        for (int p = 0; p < 8; ++p) {
            float bv = -FLT_MAX; int bk = 0x7fffffff;
            #pragma unroll
            for (int s = 0; s < 6; ++s) {
                if (!((used >> s) & 1u)) {
                    if (lv[s] > bv || (lv[s] == bv && lk[s] < bk)) {
                        bv = lv[s]; bk = lk[s];
                    }
                }
            }
            #pragma unroll
            for (int off = 16; off; off >>= 1) {
                float ov = __shfl_xor_sync(0xffffffffu, bv, off);
                int ok = __shfl_xor_sync(0xffffffffu, bk, off);
                if (ov > bv || (ov == bv && ok < bk)) { bv = ov; bk = ok; }
            }
            #pragma unroll
            for (int s = 0; s < 6; ++s)
                if (lv[s] == bv && lk[s] == bk) used |= 1u << s;
            if (lane == 0) scand[p] = bk;
        }
    }
    __syncthreads();

    const int cand = scand[wid];   // 8 warps, one candidate each
    const float4* sq4 = reinterpret_cast<const float4*>(sq);
    const float4* k4 = reinterpret_cast<const float4*>(keys) + (size_t)cand * (ND / 4);
    float acc0 = 0.0f, acc1 = 0.0f;
    #pragma unroll
    for (int u = 0; u < 8; u += 2) {
        float4 a0 = sq4[u * 32 + lane];
        float4 c0 = k4[u * 32 + lane];
        float4 a1 = sq4[(u + 1) * 32 + lane];
        float4 c1 = k4[(u + 1) * 32 + lane];
        acc0 += a0.x * c0.x + a0.y * c0.y + a0.z * c0.z + a0.w * c0.w;
        acc1 += a1.x * c1.x + a1.y * c1.y + a1.z * c1.z + a1.w * c1.w;
    }
    float acc = acc0 + acc1;
    #pragma unroll
    for (int o = 16; o; o >>= 1) acc += __shfl_xor_sync(0xffffffffu, acc, o);
    if (lane == 0) { ssim[wid] = acc * g_qinv[b] * g_kinv[cand]; sidx[wid] = cand; }
    __syncthreads();

    if (tid == 0) {
        float v[8]; int id[8];
        #pragma unroll
        for (int s = 0; s < 8; ++s) { v[s] = ssim[s]; id[s] = sidx[s]; }
        float bv[4]; int bi[4]; unsigned used = 0;
        #pragma unroll
        for (int p = 0; p < 4; ++p) {
            float best = -FLT_MAX; int besti = 0x7fffffff; int bs = 0;
            #pragma unroll
            for (int s = 0; s < 8; ++s) {
                if (!((used >> s) & 1u)) {
                    if (v[s] > best || (v[s] == best && id[s] < besti)) {
                        best = v[s]; besti = id[s]; bs = s;
                    }
                }
            }
            used |= 1u << bs; bv[p] = best; bi[p] = besti;
        }
        float e[4], sum = 0.0f;
        #pragma unroll
        for (int jx = 0; jx < 4; ++jx) { e[jx] = expf(bv[jx] - bv[0]); sum += e[jx]; }
        float inv = 1.0f / sum;
        #pragma unroll
        for (int jx = 0; jx < 4; ++jx) { sw[jx] = e[jx] * inv; si[jx] = bi[jx]; }
    }
    __syncthreads();

    const float w0 = sw[0], w1 = sw[1], w2 = sw[2], w3 = sw[3];
    const int i0 = si[0], i1 = si[1], i2 = si[2], i3 = si[3];
    const float4* v4 = reinterpret_cast<const float4*>(values);
    float4 a = v4[(size_t)i0 * (ND / 4) + tid];
    float4 bb = v4[(size_t)i1 * (ND / 4) + tid];
    float4 c = v4[(size_t)i2 * (ND / 4) + tid];
    float4 d = v4[(size_t)i3 * (ND / 4) + tid];
    float4 r;
    r.x = fmaf(w3, d.x, fmaf(w2, c.x, fmaf(w1, bb.x, w0 * a.x)));
    r.y = fmaf(w3, d.y, fmaf(w2, c.y, fmaf(w1, bb.y, w0 * a.y)));
    r.z = fmaf(w3, d.z, fmaf(w2, c.z, fmaf(w1, bb.z, w0 * a.z)));
    r.w = fmaf(w3, d.w, fmaf(w2, c.w, fmaf(w1, bb.w, w0 * a.w)));
    reinterpret_cast<float4*>(out)[(size_t)b * (ND / 4) + tid] = r;
}

// ---------------- launch ----------------
extern "C" void kernel_launch(void* const* d_in, const int* in_sizes, int n_in,
                              void* d_out, int out_size) {
    const float* query = (const float*)d_in[0];
    const float* keys = (const float*)d_in[1];
    const float* values = (const float*)d_in[2];
    // d_in[3] = k, fixed at 4 for this shape.

    cudaFuncSetAttribute(simtopk_kernel, cudaFuncAttributeMaxDynamicSharedMemorySize,
                         SMEM_BYTES);
    norm_kernel<<<NB + NKEY, 256>>>(query, keys);
    simtopk_kernel<<<NSM, THREADS, SMEM_BYTES>>>();
    rescore_kernel<<<NB, 256>>>(query, keys, values, (float*)d_out);
}

// round 14
// speedup vs baseline: 1.0355x; 1.0355x over previous
#include <cuda_runtime.h>
#include <cuda_bf16.h>
#include <cfloat>
#include <stdint.h>
#include <math.h>

#define NB 16384
#define NKEY 8192
#define ND 1024
#define BM 128
#define BN 256
#define BK 64
#define STAGES 4
#define NSM 148
#define NPAIRS 4096                // 128 qtiles x 32 keytiles
#define THREADS 512

#define ROWB 144                   // 128B data + 16B pad
#define A_BYTES (BM * ROWB)        // 18432
#define B_BYTES (BN * ROWB)        // 36864
#define STAGE_BYTES (A_BYTES + B_BYTES)   // 55296
#define SMEM_BYTES (STAGES * STAGE_BYTES) // 221184

// ---------------- scratch ----------------
__device__ __nv_bfloat16 g_qn16[(size_t)NB * ND];
__device__ __nv_bfloat16 g_kn16[(size_t)NKEY * ND];
__device__ float g_qinv[NB];
__device__ float g_kinv[NKEY];
// raw per-slice top-4 dump: [cta][seg<=2][row 128][slice 16][4] (val, idx)
__device__ float2 g_dump[(size_t)NSM * 2 * BM * 64];

// ---------------- helpers ----------------
static __device__ __forceinline__ uint32_t smem_u32(const void* p) {
    return (uint32_t)__cvta_generic_to_shared(p);
}
static __device__ __forceinline__ void cp16(uint32_t dst, const void* src) {
    asm volatile("cp.async.cg.shared.global [%0], [%1], 16;" :: "r"(dst), "l"(src));
}
static __device__ __forceinline__ void cp_commit() {
    asm volatile("cp.async.commit_group;" ::: "memory");
}
static __device__ __forceinline__ void cp_wait2() {
    asm volatile("cp.async.wait_group 2;" ::: "memory");
}
static __device__ __forceinline__ void ldm_x4(uint32_t* r, uint32_t a) {
    asm volatile("ldmatrix.sync.aligned.m8n8.x4.shared.b16 {%0,%1,%2,%3}, [%4];"
                 : "=r"(r[0]), "=r"(r[1]), "=r"(r[2]), "=r"(r[3]) : "r"(a));
}
static __device__ __forceinline__ void mma16816(float* d, const uint32_t* a,
                                                const uint32_t* b) {
    asm volatile(
        "mma.sync.aligned.m16n8k16.row.col.f32.bf16.bf16.f32 "
        "{%0,%1,%2,%3}, {%4,%5,%6,%7}, {%8,%9}, {%0,%1,%2,%3};"
        : "+f"(d[0]), "+f"(d[1]), "+f"(d[2]), "+f"(d[3])
        : "r"(a[0]), "r"(a[1]), "r"(a[2]), "r"(a[3]), "r"(b[0]), "r"(b[1]));
}

// ------- normalize -> bf16 (queries + keys fused; 128 thr/row, 8 elts/thr) -------
__global__ void norm_kernel(const float* __restrict__ q, const float* __restrict__ k) {
    int row = blockIdx.x;
    const float* in;
    __nv_bfloat16* out;
    float* invp;
    int r;
    if (row < NB) { in = q; out = g_qn16; invp = g_qinv; r = row; }
    else          { in = k; out = g_kn16; invp = g_kinv; r = row - NB; }
    int t = threadIdx.x;   // 128 threads, two float4 each
    const float4* in4 = reinterpret_cast<const float4*>(in) + (size_t)r * (ND / 4);
    float4 v0 = in4[t];
    float4 v1 = in4[t + 128];
    float ss = v0.x * v0.x + v0.y * v0.y + v0.z * v0.z + v0.w * v0.w
             + v1.x * v1.x + v1.y * v1.y + v1.z * v1.z + v1.w * v1.w;
    #pragma unroll
    for (int o = 16; o; o >>= 1) ss += __shfl_xor_sync(0xffffffffu, ss, o);
    __shared__ float wsum[4];
    if ((t & 31) == 0) wsum[t >> 5] = ss;
    __syncthreads();
    float tot = wsum[0] + wsum[1] + wsum[2] + wsum[3];
    float inv = 1.0f / fmaxf(sqrtf(tot), 1e-12f);
    if (t == 0) invp[r] = inv;
    union { __nv_bfloat162 h2[2]; uint2 u; } p0, p1;
    p0.h2[0] = __floats2bfloat162_rn(v0.x * inv, v0.y * inv);
    p0.h2[1] = __floats2bfloat162_rn(v0.z * inv, v0.w * inv);
    p1.h2[0] = __floats2bfloat162_rn(v1.x * inv, v1.y * inv);
    p1.h2[1] = __floats2bfloat162_rn(v1.z * inv, v1.w * inv);
    uint2* o2 = reinterpret_cast<uint2*>(out) + (size_t)r * (ND / 4);
    o2[t] = p0.u;
    o2[t + 128] = p1.u;
}

// ---------------- top-4 insert ----------------
static __device__ __forceinline__ void top4_insert(float* tv, int* ti, float v, int idx) {
    if (v > tv[3]) {
        tv[3] = v; ti[3] = idx;
        #pragma unroll
        for (int s = 3; s > 0; --s) {
            if (tv[s] > tv[s - 1]) {
                float tf = tv[s]; tv[s] = tv[s - 1]; tv[s - 1] = tf;
                int tn = ti[s]; ti[s] = ti[s - 1]; ti[s - 1] = tn;
            }
        }
    }
}

// ---- bf16 sim GEMM: 148 CTAs over 4096 (qtile,keytile) pairs, raw dump ----
__global__ __launch_bounds__(THREADS, 1) void simtopk_kernel() {
    extern __shared__ char dynsmem[];
    const uint32_t sbase = smem_u32(dynsmem);
    const int tid = threadIdx.x;
    const int wid = tid >> 5, lane = tid & 31;
    const int warp_m = wid & 3;     // rows warp_m*32
    const int warp_n = wid >> 2;    // cols warp_n*64
    const int cta = blockIdx.x;

    const int p0 = (cta * NPAIRS) / NSM;
    const int p1 = ((cta + 1) * NPAIRS) / NSM;
    const int nsteps = (p1 - p0) * 16;

    float acc[2][8][4];
    float tv[4][4]; int ti[4][4];
    #pragma unroll
    for (int mf = 0; mf < 2; ++mf)
        #pragma unroll
        for (int nf = 0; nf < 8; ++nf)
            #pragma unroll
            for (int e = 0; e < 4; ++e) acc[mf][nf][e] = 0.0f;
    #pragma unroll
    for (int r = 0; r < 4; ++r)
        #pragma unroll
        for (int e = 0; e < 4; ++e) { tv[r][e] = -FLT_MAX; ti[r][e] = 0; }

    auto issue_loads = [&](int j) {
        const int pair = p0 + (j >> 4);
        const int qb = (pair >> 5) * BM;
        const int kb = (pair & 31) * BN;
        const int kcol = (j & 15) * BK;
        const uint32_t aS = sbase + (uint32_t)(j & 3) * STAGE_BYTES;
        const uint32_t bS = aS + A_BYTES;
        #pragma unroll
        for (int u = 0; u < 2; ++u) {   // A: 128 rows x 8 chunks of 16B
            int idx = tid + 512 * u;
            int row = idx >> 3, c = idx & 7;
            cp16(aS + row * ROWB + c * 16,
                 g_qn16 + (size_t)(qb + row) * ND + kcol + c * 8);
        }
        #pragma unroll
        for (int u = 0; u < 4; ++u) {   // B: 256 rows x 8 chunks
            int idx = tid + 512 * u;
            int row = idx >> 3, c = idx & 7;
            cp16(bS + row * ROWB + c * 16,
                 g_kn16 + (size_t)(kb + row) * ND + kcol + c * 8);
        }
    };

    #pragma unroll
    for (int j = 0; j < STAGES - 1; ++j) { issue_loads(j); cp_commit(); }

    for (int i = 0; i < nsteps; ++i) {
        cp_wait2();
        __syncthreads();
        if (i + 3 < nsteps) issue_loads(i + 3);
        cp_commit();

        const uint32_t aS = sbase + (uint32_t)(i & 3) * STAGE_BYTES;
        const uint32_t bS = aS + A_BYTES;
        const uint32_t aAddr = aS + (warp_m * 32 + (lane & 15)) * ROWB + (lane >> 4) * 16;
        const uint32_t bAddr = bS + (warp_n * 64 + (lane & 7) + (lane >> 4) * 8) * ROWB
                               + ((lane >> 3) & 1) * 16;
        #pragma unroll
        for (int kf = 0; kf < 4; ++kf) {
            uint32_t af[2][4];
            ldm_x4(af[0], aAddr + kf * 32);
            ldm_x4(af[1], aAddr + 16 * ROWB + kf * 32);
            #pragma unroll
            for (int ng = 0; ng < 4; ++ng) {
                uint32_t bf[4];
                ldm_x4(bf, bAddr + ng * 16 * ROWB + kf * 32);
                mma16816(acc[0][2 * ng],     af[0], bf + 0);
                mma16816(acc[0][2 * ng + 1], af[0], bf + 2);
                mma16816(acc[1][2 * ng],     af[1], bf + 0);
                mma16816(acc[1][2 * ng + 1], af[1], bf + 2);
            }
        }

        if ((i & 15) == 15) {   // keytile done: fold into per-slice top-4
            const int pair = p0 + (i >> 4);
            const int cb = (pair & 31) * BN + warp_n * 64 + (lane & 3) * 2;
            #pragma unroll
            for (int mf = 0; mf < 2; ++mf)
                #pragma unroll
                for (int nf = 0; nf < 8; ++nf) {
                    float* a4 = acc[mf][nf];
                    const int cc = cb + nf * 8;
                    top4_insert(tv[mf * 2],     ti[mf * 2],     a4[0], cc);
                    top4_insert(tv[mf * 2],     ti[mf * 2],     a4[1], cc + 1);
                    top4_insert(tv[mf * 2 + 1], ti[mf * 2 + 1], a4[2], cc);
                    top4_insert(tv[mf * 2 + 1], ti[mf * 2 + 1], a4[3], cc + 1);
                    a4[0] = a4[1] = a4[2] = a4[3] = 0.0f;
                }
            // segment (qtile) boundary or end: raw-dump tv/ti, reset
            if (i == nsteps - 1 || (((pair + 1) >> 5) != (pair >> 5))) {
                const int seg = (pair >> 5) - (p0 >> 5);   // 0 or 1
                const int slice = warp_n * 4 + (lane & 3);
                #pragma unroll
                for (int rp = 0; rp < 4; ++rp) {
                    int row = warp_m * 32 + (rp >> 1) * 16 + (rp & 1) * 8 + (lane >> 2);
                    size_t base = ((size_t)(cta * 2 + seg) * BM + row) * 64 + slice * 4;
                    #pragma unroll
                    for (int e = 0; e < 4; ++e)
                        g_dump[base + e] = make_float2(tv[rp][e],
                                                       __int_as_float(ti[rp][e]));
                }
                #pragma unroll
                for (int r = 0; r < 4; ++r)
                    #pragma unroll
                    for (int e = 0; e < 4; ++e) { tv[r][e] = -FLT_MAX; ti[r][e] = 0; }
            }
        }
    }
}

// ------- rescore: merge covering-CTA dumps -> bf16 top-8 -> fp32 top-4 -------
__global__ __launch_bounds__(256, 4) void rescore_kernel(const float* __restrict__ q,
                                                         const float* __restrict__ keys,
                                                         const float* __restrict__ values,
                                                         float* __restrict__ out) {
    const int b = blockIdx.x;
    const int qt = b >> 7, row = b & 127;
    const int tid = threadIdx.x, wid = tid >> 5, lane = tid & 31;
    __shared__ int scand[8];
    __shared__ float ssim[8];
    __shared__ int sidx[8];
    __shared__ float sw[4];
    __shared__ int si[4];

    if (tid < 32) {   // one warp merges up to 3 covering CTAs x 64 entries
        const int pfirst = qt * 32, plast = pfirst + 31;
        int cmin = (pfirst * NSM) >> 12;
        while ((cmin + 1) * NPAIRS / NSM <= pfirst) ++cmin;
        while (cmin * NPAIRS / NSM > pfirst) --cmin;
        int cmax = (plast * NSM) >> 12;
        while ((cmax + 1) * NPAIRS / NSM <= plast) ++cmax;
        while (cmax * NPAIRS / NSM > plast) --cmax;
        const int ncov = cmax - cmin + 1;      // 2 or 3

        float lv[6]; int lk[6];
        #pragma unroll
        for (int s = 0; s < 6; ++s) { lv[s] = -FLT_MAX; lk[s] = 0x7fffffff; }
        for (int ci = 0; ci < ncov; ++ci) {
            int c = cmin + ci;
            int p0c = c * NPAIRS / NSM;
            int seg = qt - (p0c >> 5);
            const float2* base = g_dump + ((size_t)(c * 2 + seg) * BM + row) * 64;
            float2 e0 = base[lane * 2];
            float2 e1 = base[lane * 2 + 1];
            lv[ci * 2] = e0.x;     lk[ci * 2] = __float_as_int(e0.y);
            lv[ci * 2 + 1] = e1.x; lk[ci * 2 + 1] = __float_as_int(e1.y);
        }
        unsigned used = 0;
        for (int p = 0; p < 8; ++p) {
            float bv = -FLT_MAX; int bk = 0x7fffffff;
            #pragma unroll
            for (int s = 0; s < 6; ++s) {
                if (!((used >> s) & 1u)) {
                    if (lv[s] > bv || (lv[s] == bv && lk[s] < bk)) {
                        bv = lv[s]; bk = lk[s];
                    }
                }
            }
            #pragma unroll
            for (int off = 16; off; off >>= 1) {
                float ov = __shfl_xor_sync(0xffffffffu, bv, off);
                int ok = __shfl_xor_sync(0xffffffffu, bk, off);
                if (ov > bv || (ov == bv && ok < bk)) { bv = ov; bk = ok; }
            }
            #pragma unroll
            for (int s = 0; s < 6; ++s)
                if (lv[s] == bv && lk[s] == bk) used |= 1u << s;
            if (lane == 0) scand[p] = bk;
        }
    }
    __syncthreads();

    const int cand = scand[wid];   // 8 warps, one candidate each
    const float4* q4 = reinterpret_cast<const float4*>(q) + (size_t)b * (ND / 4);
    const float4* k4 = reinterpret_cast<const float4*>(keys) + (size_t)cand * (ND / 4);
    float acc = 0.0f;
    #pragma unroll 4
    for (int u = 0; u < 8; ++u) {
        float4 a = q4[u * 32 + lane];
        float4 c = k4[u * 32 + lane];
        acc += a.x * c.x + a.y * c.y + a.z * c.z + a.w * c.w;
    }
    #pragma unroll
    for (int o = 16; o; o >>= 1) acc += __shfl_xor_sync(0xffffffffu, acc, o);
    if (lane == 0) { ssim[wid] = acc * g_qinv[b] * g_kinv[cand]; sidx[wid] = cand; }
    __syncthreads();

    if (tid == 0) {
        float v[8]; int id[8];
        #pragma unroll
        for (int s = 0; s < 8; ++s) { v[s] = ssim[s]; id[s] = sidx[s]; }
        float bv[4]; int bi[4]; unsigned used = 0;
        #pragma unroll
        for (int p = 0; p < 4; ++p) {
            float best = -FLT_MAX; int besti = 0x7fffffff; int bs = 0;
            #pragma unroll
            for (int s = 0; s < 8; ++s) {
                if (!((used >> s) & 1u)) {
                    if (v[s] > best || (v[s] == best && id[s] < besti)) {
                        best = v[s]; besti = id[s]; bs = s;
                    }
                }
            }
            used |= 1u << bs; bv[p] = best; bi[p] = besti;
        }
        float e[4], sum = 0.0f;
        #pragma unroll
        for (int jx = 0; jx < 4; ++jx) { e[jx] = expf(bv[jx] - bv[0]); sum += e[jx]; }
        float inv = 1.0f / sum;
        #pragma unroll
        for (int jx = 0; jx < 4; ++jx) { sw[jx] = e[jx] * inv; si[jx] = bi[jx]; }
    }
    __syncthreads();

    const float w0 = sw[0], w1 = sw[1], w2 = sw[2], w3 = sw[3];
    const int i0 = si[0], i1 = si[1], i2 = si[2], i3 = si[3];
    const float4* v4 = reinterpret_cast<const float4*>(values);
    float4 a = v4[(size_t)i0 * (ND / 4) + tid];
    float4 bb = v4[(size_t)i1 * (ND / 4) + tid];
    float4 c = v4[(size_t)i2 * (ND / 4) + tid];
    float4 d = v4[(size_t)i3 * (ND / 4) + tid];
    float4 r;
    r.x = fmaf(w3, d.x, fmaf(w2, c.x, fmaf(w1, bb.x, w0 * a.x)));
    r.y = fmaf(w3, d.y, fmaf(w2, c.y, fmaf(w1, bb.y, w0 * a.y)));
    r.z = fmaf(w3, d.z, fmaf(w2, c.z, fmaf(w1, bb.z, w0 * a.z)));
    r.w = fmaf(w3, d.w, fmaf(w2, c.w, fmaf(w1, bb.w, w0 * a.w)));
    reinterpret_cast<float4*>(out)[(size_t)b * (ND / 4) + tid] = r;
}

// ---------------- launch ----------------
extern "C" void kernel_launch(void* const* d_in, const int* in_sizes, int n_in,
                              void* d_out, int out_size) {
    const float* query = (const float*)d_in[0];
    const float* keys = (const float*)d_in[1];
    const float* values = (const float*)d_in[2];
    // d_in[3] = k, fixed at 4 for this shape.

    cudaFuncSetAttribute(simtopk_kernel, cudaFuncAttributeMaxDynamicSharedMemorySize,
                         SMEM_BYTES);
    norm_kernel<<<NB + NKEY, 128>>>(query, keys);
    simtopk_kernel<<<NSM, THREADS, SMEM_BYTES>>>();
    rescore_kernel<<<NB, 256>>>(query, keys, values, (float*)d_out);
}

// round 15
// speedup vs baseline: 1.0369x; 1.0014x over previous
#include <cuda_runtime.h>
#include <cuda_bf16.h>
#include <cfloat>
#include <stdint.h>
#include <math.h>

#define NB 16384
#define NKEY 8192
#define ND 1024
#define BM 128
#define BN 256
#define BK 64
#define STAGES 4
#define NSM 148
#define NPAIRS 4096                // 128 qtiles x 32 keytiles
#define THREADS 512

#define ROWB 144                   // 128B data + 16B pad
#define A_BYTES (BM * ROWB)        // 18432
#define B_BYTES (BN * ROWB)        // 36864
#define STAGE_BYTES (A_BYTES + B_BYTES)   // 55296
#define SMEM_BYTES (STAGES * STAGE_BYTES) // 221184

// ---------------- scratch ----------------
__device__ __nv_bfloat16 g_qn16[(size_t)NB * ND];
__device__ __nv_bfloat16 g_kn16[(size_t)NKEY * ND];
__device__ float g_qinv[NB];
__device__ float g_kinv[NKEY];
// raw per-slice top-4 dump: [cta][seg<=2][row 128][slice 16][4] (val, idx)
__device__ float2 g_dump[(size_t)NSM * 2 * BM * 64];

// ---------------- helpers ----------------
static __device__ __forceinline__ uint32_t smem_u32(const void* p) {
    return (uint32_t)__cvta_generic_to_shared(p);
}
static __device__ __forceinline__ void cp16(uint32_t dst, const void* src) {
    asm volatile("cp.async.cg.shared.global [%0], [%1], 16;" :: "r"(dst), "l"(src));
}
static __device__ __forceinline__ void cp_commit() {
    asm volatile("cp.async.commit_group;" ::: "memory");
}
static __device__ __forceinline__ void cp_wait2() {
    asm volatile("cp.async.wait_group 2;" ::: "memory");
}
static __device__ __forceinline__ void ldm_x4(uint32_t* r, uint32_t a) {
    asm volatile("ldmatrix.sync.aligned.m8n8.x4.shared.b16 {%0,%1,%2,%3}, [%4];"
                 : "=r"(r[0]), "=r"(r[1]), "=r"(r[2]), "=r"(r[3]) : "r"(a));
}
static __device__ __forceinline__ void mma16816(float* d, const uint32_t* a,
                                                const uint32_t* b) {
    asm volatile(
        "mma.sync.aligned.m16n8k16.row.col.f32.bf16.bf16.f32 "
        "{%0,%1,%2,%3}, {%4,%5,%6,%7}, {%8,%9}, {%0,%1,%2,%3};"
        : "+f"(d[0]), "+f"(d[1]), "+f"(d[2]), "+f"(d[3])
        : "r"(a[0]), "r"(a[1]), "r"(a[2]), "r"(a[3]), "r"(b[0]), "r"(b[1]));
}

// ------- normalize -> bf16 (queries + keys fused; 128 thr/row, 8 elts/thr) -------
__global__ void norm_kernel(const float* __restrict__ q, const float* __restrict__ k) {
    int row = blockIdx.x;
    const float* in;
    __nv_bfloat16* out;
    float* invp;
    int r;
    if (row < NB) { in = q; out = g_qn16; invp = g_qinv; r = row; }
    else          { in = k; out = g_kn16; invp = g_kinv; r = row - NB; }
    int t = threadIdx.x;   // 128 threads, two float4 each
    const float4* in4 = reinterpret_cast<const float4*>(in) + (size_t)r * (ND / 4);
    float4 v0 = in4[t];
    float4 v1 = in4[t + 128];
    float ss = v0.x * v0.x + v0.y * v0.y + v0.z * v0.z + v0.w * v0.w
             + v1.x * v1.x + v1.y * v1.y + v1.z * v1.z + v1.w * v1.w;
    #pragma unroll
    for (int o = 16; o; o >>= 1) ss += __shfl_xor_sync(0xffffffffu, ss, o);
    __shared__ float wsum[4];
    if ((t & 31) == 0) wsum[t >> 5] = ss;
    __syncthreads();
    float tot = wsum[0] + wsum[1] + wsum[2] + wsum[3];
    float inv = 1.0f / fmaxf(sqrtf(tot), 1e-12f);
    if (t == 0) invp[r] = inv;
    union { __nv_bfloat162 h2[2]; uint2 u; } p0, p1;
    p0.h2[0] = __floats2bfloat162_rn(v0.x * inv, v0.y * inv);
    p0.h2[1] = __floats2bfloat162_rn(v0.z * inv, v0.w * inv);
    p1.h2[0] = __floats2bfloat162_rn(v1.x * inv, v1.y * inv);
    p1.h2[1] = __floats2bfloat162_rn(v1.z * inv, v1.w * inv);
    uint2* o2 = reinterpret_cast<uint2*>(out) + (size_t)r * (ND / 4);
    o2[t] = p0.u;
    o2[t + 128] = p1.u;
}

// ---------------- top-4 insert ----------------
static __device__ __forceinline__ void top4_insert(float* tv, int* ti, float v, int idx) {
    if (v > tv[3]) {
        tv[3] = v; ti[3] = idx;
        #pragma unroll
        for (int s = 3; s > 0; --s) {
            if (tv[s] > tv[s - 1]) {
                float tf = tv[s]; tv[s] = tv[s - 1]; tv[s - 1] = tf;
                int tn = ti[s]; ti[s] = ti[s - 1]; ti[s - 1] = tn;
            }
        }
    }
}

// ---- bf16 sim GEMM: 148 CTAs over 4096 (qtile,keytile) pairs, raw dump ----
__global__ __launch_bounds__(THREADS, 1) void simtopk_kernel() {
    extern __shared__ char dynsmem[];
    const uint32_t sbase = smem_u32(dynsmem);
    const int tid = threadIdx.x;
    const int wid = tid >> 5, lane = tid & 31;
    const int warp_m = wid & 3;     // rows warp_m*32
    const int warp_n = wid >> 2;    // cols warp_n*64
    const int cta = blockIdx.x;

    const int p0 = (cta * NPAIRS) / NSM;
    const int p1 = ((cta + 1) * NPAIRS) / NSM;
    const int nsteps = (p1 - p0) * 16;

    float acc[2][8][4];
    float tv[4][4]; int ti[4][4];
    #pragma unroll
    for (int mf = 0; mf < 2; ++mf)
        #pragma unroll
        for (int nf = 0; nf < 8; ++nf)
            #pragma unroll
            for (int e = 0; e < 4; ++e) acc[mf][nf][e] = 0.0f;
    #pragma unroll
    for (int r = 0; r < 4; ++r)
        #pragma unroll
        for (int e = 0; e < 4; ++e) { tv[r][e] = -FLT_MAX; ti[r][e] = 0; }

    auto issue_loads = [&](int j) {
        const int pair = p0 + (j >> 4);
        const int qb = (pair >> 5) * BM;
        const int kb = (pair & 31) * BN;
        const int kcol = (j & 15) * BK;
        const uint32_t aS = sbase + (uint32_t)(j & 3) * STAGE_BYTES;
        const uint32_t bS = aS + A_BYTES;
        #pragma unroll
        for (int u = 0; u < 2; ++u) {   // A: 128 rows x 8 chunks of 16B
            int idx = tid + 512 * u;
            int row = idx >> 3, c = idx & 7;
            cp16(aS + row * ROWB + c * 16,
                 g_qn16 + (size_t)(qb + row) * ND + kcol + c * 8);
        }
        #pragma unroll
        for (int u = 0; u < 4; ++u) {   // B: 256 rows x 8 chunks
            int idx = tid + 512 * u;
            int row = idx >> 3, c = idx & 7;
            cp16(bS + row * ROWB + c * 16,
                 g_kn16 + (size_t)(kb + row) * ND + kcol + c * 8);
        }
    };

    #pragma unroll
    for (int j = 0; j < STAGES - 1; ++j) { issue_loads(j); cp_commit(); }

    for (int i = 0; i < nsteps; ++i) {
        cp_wait2();
        __syncthreads();
        if (i + 3 < nsteps) issue_loads(i + 3);
        cp_commit();

        const uint32_t aS = sbase + (uint32_t)(i & 3) * STAGE_BYTES;
        const uint32_t bS = aS + A_BYTES;
        const uint32_t aAddr = aS + (warp_m * 32 + (lane & 15)) * ROWB + (lane >> 4) * 16;
        const uint32_t bAddr = bS + (warp_n * 64 + (lane & 7) + (lane >> 4) * 8) * ROWB
                               + ((lane >> 3) & 1) * 16;
        #pragma unroll
        for (int kf = 0; kf < 4; ++kf) {
            uint32_t af[2][4];
            ldm_x4(af[0], aAddr + kf * 32);
            ldm_x4(af[1], aAddr + 16 * ROWB + kf * 32);
            #pragma unroll
            for (int ng = 0; ng < 4; ++ng) {
                uint32_t bf[4];
                ldm_x4(bf, bAddr + ng * 16 * ROWB + kf * 32);
                mma16816(acc[0][2 * ng],     af[0], bf + 0);
                mma16816(acc[0][2 * ng + 1], af[0], bf + 2);
                mma16816(acc[1][2 * ng],     af[1], bf + 0);
                mma16816(acc[1][2 * ng + 1], af[1], bf + 2);
            }
        }

        if ((i & 15) == 15) {   // keytile done: fold into per-slice top-4
            const int pair = p0 + (i >> 4);
            const int cb = (pair & 31) * BN + warp_n * 64 + (lane & 3) * 2;
            #pragma unroll
            for (int mf = 0; mf < 2; ++mf)
                #pragma unroll
                for (int nf = 0; nf < 8; ++nf) {
                    float* a4 = acc[mf][nf];
                    const int cc = cb + nf * 8;
                    top4_insert(tv[mf * 2],     ti[mf * 2],     a4[0], cc);
                    top4_insert(tv[mf * 2],     ti[mf * 2],     a4[1], cc + 1);
                    top4_insert(tv[mf * 2 + 1], ti[mf * 2 + 1], a4[2], cc);
                    top4_insert(tv[mf * 2 + 1], ti[mf * 2 + 1], a4[3], cc + 1);
                    a4[0] = a4[1] = a4[2] = a4[3] = 0.0f;
                }
            // segment (qtile) boundary or end: raw-dump tv/ti, reset
            if (i == nsteps - 1 || (((pair + 1) >> 5) != (pair >> 5))) {
                const int seg = (pair >> 5) - (p0 >> 5);   // 0 or 1
                const int slice = warp_n * 4 + (lane & 3);
                #pragma unroll
                for (int rp = 0; rp < 4; ++rp) {
                    int row = warp_m * 32 + (rp >> 1) * 16 + (rp & 1) * 8 + (lane >> 2);
                    size_t base = ((size_t)(cta * 2 + seg) * BM + row) * 64 + slice * 4;
                    #pragma unroll
                    for (int e = 0; e < 4; ++e)
                        g_dump[base + e] = make_float2(tv[rp][e],
                                                       __int_as_float(ti[rp][e]));
                }
                #pragma unroll
                for (int r = 0; r < 4; ++r)
                    #pragma unroll
                    for (int e = 0; e < 4; ++e) { tv[r][e] = -FLT_MAX; ti[r][e] = 0; }
            }
        }
    }
}

// ------- rescore: merge covering-CTA dumps -> bf16 top-8 -> fp32 top-4 -------
__global__ __launch_bounds__(256, 4) void rescore_kernel(const float* __restrict__ q,
                                                         const float* __restrict__ keys,
                                                         const float* __restrict__ values,
                                                         float* __restrict__ out) {
    const int b = blockIdx.x;
    const int qt = b >> 7, row = b & 127;
    const int tid = threadIdx.x, wid = tid >> 5, lane = tid & 31;
    __shared__ int scand[8];
    __shared__ float ssim[8];
    __shared__ int sidx[8];
    __shared__ float sw[4];
    __shared__ int si[4];

    if (tid < 32) {   // one warp merges up to 3 covering CTAs x 64 entries
        const int pfirst = qt * 32, plast = pfirst + 31;
        int cmin = (pfirst * NSM) >> 12;
        while ((cmin + 1) * NPAIRS / NSM <= pfirst) ++cmin;
        while (cmin * NPAIRS / NSM > pfirst) --cmin;
        int cmax = (plast * NSM) >> 12;
        while ((cmax + 1) * NPAIRS / NSM <= plast) ++cmax;
        while (cmax * NPAIRS / NSM > plast) --cmax;
        const int ncov = cmax - cmin + 1;      // 2 or 3

        float lv[6]; int lk[6];
        #pragma unroll
        for (int s = 0; s < 6; ++s) { lv[s] = -FLT_MAX; lk[s] = 0x7fffffff; }
        for (int ci = 0; ci < ncov; ++ci) {
            int c = cmin + ci;
            int p0c = c * NPAIRS / NSM;
            int seg = qt - (p0c >> 5);
            const float2* base = g_dump + ((size_t)(c * 2 + seg) * BM + row) * 64;
            float2 e0 = base[lane * 2];
            float2 e1 = base[lane * 2 + 1];
            lv[ci * 2] = e0.x;     lk[ci * 2] = __float_as_int(e0.y);
            lv[ci * 2 + 1] = e1.x; lk[ci * 2 + 1] = __float_as_int(e1.y);
        }
        unsigned used = 0;
        for (int p = 0; p < 8; ++p) {
            float bv = -FLT_MAX; int bk = 0x7fffffff;
            #pragma unroll
            for (int s = 0; s < 6; ++s) {
                if (!((used >> s) & 1u)) {
                    if (lv[s] > bv || (lv[s] == bv && lk[s] < bk)) {
                        bv = lv[s]; bk = lk[s];
                    }
                }
            }
            #pragma unroll
            for (int off = 16; off; off >>= 1) {
                float ov = __shfl_xor_sync(0xffffffffu, bv, off);
                int ok = __shfl_xor_sync(0xffffffffu, bk, off);
                if (ov > bv || (ov == bv && ok < bk)) { bv = ov; bk = ok; }
            }
            #pragma unroll
            for (int s = 0; s < 6; ++s)
                if (lv[s] == bv && lk[s] == bk) used |= 1u << s;
            if (lane == 0) scand[p] = bk;
        }
    }
    __syncthreads();

    const int cand = scand[wid];   // 8 warps, one candidate each
    const float4* q4 = reinterpret_cast<const float4*>(q) + (size_t)b * (ND / 4);
    const float4* k4 = reinterpret_cast<const float4*>(keys) + (size_t)cand * (ND / 4);
    float acc = 0.0f;
    #pragma unroll 4
    for (int u = 0; u < 8; ++u) {
        float4 a = q4[u * 32 + lane];
        float4 c = k4[u * 32 + lane];
        acc += a.x * c.x + a.y * c.y + a.z * c.z + a.w * c.w;
    }
    #pragma unroll
    for (int o = 16; o; o >>= 1) acc += __shfl_xor_sync(0xffffffffu, acc, o);
    if (lane == 0) { ssim[wid] = acc * g_qinv[b] * g_kinv[cand]; sidx[wid] = cand; }
    __syncthreads();

    if (tid == 0) {
        float v[8]; int id[8];
        #pragma unroll
        for (int s = 0; s < 8; ++s) { v[s] = ssim[s]; id[s] = sidx[s]; }
        float bv[4]; int bi[4]; unsigned used = 0;
        #pragma unroll
        for (int p = 0; p < 4; ++p) {
            float best = -FLT_MAX; int besti = 0x7fffffff; int bs = 0;
            #pragma unroll
            for (int s = 0; s < 8; ++s) {
                if (!((used >> s) & 1u)) {
                    if (v[s] > best || (v[s] == best && id[s] < besti)) {
                        best = v[s]; besti = id[s]; bs = s;
                    }
                }
            }
            used |= 1u << bs; bv[p] = best; bi[p] = besti;
        }
        float e[4], sum = 0.0f;
        #pragma unroll
        for (int jx = 0; jx < 4; ++jx) { e[jx] = expf(bv[jx] - bv[0]); sum += e[jx]; }
        float inv = 1.0f / sum;
        #pragma unroll
        for (int jx = 0; jx < 4; ++jx) { sw[jx] = e[jx] * inv; si[jx] = bi[jx]; }
    }
    __syncthreads();

    const float w0 = sw[0], w1 = sw[1], w2 = sw[2], w3 = sw[3];
    const int i0 = si[0], i1 = si[1], i2 = si[2], i3 = si[3];
    const float4* v4 = reinterpret_cast<const float4*>(values);
    float4 a = v4[(size_t)i0 * (ND / 4) + tid];
    float4 bb = v4[(size_t)i1 * (ND / 4) + tid];
    float4 c = v4[(size_t)i2 * (ND / 4) + tid];
    float4 d = v4[(size_t)i3 * (ND / 4) + tid];
    float4 r;
    r.x = fmaf(w3, d.x, fmaf(w2, c.x, fmaf(w1, bb.x, w0 * a.x)));
    r.y = fmaf(w3, d.y, fmaf(w2, c.y, fmaf(w1, bb.y, w0 * a.y)));
    r.z = fmaf(w3, d.z, fmaf(w2, c.z, fmaf(w1, bb.z, w0 * a.z)));
    r.w = fmaf(w3, d.w, fmaf(w2, c.w, fmaf(w1, bb.w, w0 * a.w)));
    reinterpret_cast<float4*>(out)[(size_t)b * (ND / 4) + tid] = r;
}

// ---------------- launch ----------------
extern "C" void kernel_launch(void* const* d_in, const int* in_sizes, int n_in,
                              void* d_out, int out_size) {
    const float* query = (const float*)d_in[0];
    const float* keys = (const float*)d_in[1];
    const float* values = (const float*)d_in[2];
    // d_in[3] = k, fixed at 4 for this shape.

    cudaFuncSetAttribute(simtopk_kernel, cudaFuncAttributeMaxDynamicSharedMemorySize,
                         SMEM_BYTES);
    norm_kernel<<<NB + NKEY, 128>>>(query, keys);
    simtopk_kernel<<<NSM, THREADS, SMEM_BYTES>>>();
    rescore_kernel<<<NB, 256>>>(query, keys, values, (float*)d_out);
}